// round 15
// baseline (speedup 1.0000x reference)
#include <cuda_runtime.h>
#include <cuda_bf16.h>
#include <math.h>
#include <stdint.h>
#include <string.h>

// ---------------- problem constants ----------------
#define LAYERS 6
#define BATCH  4
#define SEQ    1024
#define DM     768
#define NH     16
#define HDIM   48
#define FFDIM  3072
#define MTOK   (BATCH*SEQ)   // 4096

typedef unsigned long long u64;
typedef __nv_bfloat16  bf16;
typedef __nv_bfloat162 bf162;

// ---------------- mma.sync / ldmatrix / cp.async helpers --------------------
__device__ __forceinline__ uint32_t smem_u32(const void* p) {
    uint32_t a;
    asm("{ .reg .u64 t; cvta.to.shared.u64 t, %1; cvt.u32.u64 %0, t; }"
        : "=r"(a) : "l"(p));
    return a;
}
__device__ __forceinline__ void cp16(uint32_t dst, const void* src) {
    asm volatile("cp.async.cg.shared.global [%0], [%1], 16;" :: "r"(dst), "l"(src));
}
#define CP_COMMIT() asm volatile("cp.async.commit_group;" ::: "memory")
#define CP_WAIT1()  asm volatile("cp.async.wait_group 1;" ::: "memory")
#define CP_WAIT0()  asm volatile("cp.async.wait_group 0;" ::: "memory")

__device__ __forceinline__ void ldsm4(uint32_t &r0, uint32_t &r1,
                                      uint32_t &r2, uint32_t &r3, uint32_t addr) {
    asm volatile("ldmatrix.sync.aligned.m8n8.x4.shared.b16 {%0,%1,%2,%3}, [%4];"
                 : "=r"(r0), "=r"(r1), "=r"(r2), "=r"(r3) : "r"(addr));
}
__device__ __forceinline__ void ldsm4t(uint32_t &r0, uint32_t &r1,
                                       uint32_t &r2, uint32_t &r3, uint32_t addr) {
    asm volatile("ldmatrix.sync.aligned.m8n8.x4.trans.shared.b16 {%0,%1,%2,%3}, [%4];"
                 : "=r"(r0), "=r"(r1), "=r"(r2), "=r"(r3) : "r"(addr));
}
__device__ __forceinline__ void mma16816(float* d, const uint32_t* a,
                                         const uint32_t* b) {
    asm volatile("mma.sync.aligned.m16n8k16.row.col.f32.bf16.bf16.f32 "
        "{%0,%1,%2,%3}, {%4,%5,%6,%7}, {%8,%9}, {%0,%1,%2,%3};"
        : "+f"(d[0]), "+f"(d[1]), "+f"(d[2]), "+f"(d[3])
        : "r"(a[0]), "r"(a[1]), "r"(a[2]), "r"(a[3]), "r"(b[0]), "r"(b[1]));
}

// ---------------- scratch (device globals) ----------------------------------
__device__ __align__(16) float g_x   [MTOK*DM];
__device__ __align__(16) float g_gate[MTOK*FFDIM];

__device__ __align__(16) bf16 g_qkvh[MTOK*3*DM];
__device__ __align__(16) bf16 g_qkvl[MTOK*3*DM];

__device__ __align__(16) bf16 g_h_hi [MTOK*DM];
__device__ __align__(16) bf16 g_h_lo [MTOK*DM];
__device__ __align__(16) bf16 g_at_hi[MTOK*DM];
__device__ __align__(16) bf16 g_at_lo[MTOK*DM];
__device__ __align__(16) bf16 g_g_hi [MTOK*FFDIM];
__device__ __align__(16) bf16 g_g_lo [MTOK*FFDIM];

__device__ __align__(16) bf16 g_wqkv_hi[LAYERS*3*DM*DM];
__device__ __align__(16) bf16 g_wqkv_lo[LAYERS*3*DM*DM];
__device__ __align__(16) bf16 g_wo_hi  [LAYERS*DM*DM];
__device__ __align__(16) bf16 g_wo_lo  [LAYERS*DM*DM];
__device__ __align__(16) bf16 g_wg_hi  [LAYERS*FFDIM*DM];
__device__ __align__(16) bf16 g_wg_lo  [LAYERS*FFDIM*DM];
__device__ __align__(16) bf16 g_wu_hi  [LAYERS*FFDIM*DM];
__device__ __align__(16) bf16 g_wu_lo  [LAYERS*FFDIM*DM];
__device__ __align__(16) bf16 g_wd_hi  [LAYERS*DM*FFDIM];
__device__ __align__(16) bf16 g_wd_lo  [LAYERS*DM*FFDIM];

// ---------------- split helpers ---------------------------------------------
__device__ __forceinline__ void split1(float x, bf16 &h, bf16 &l) {
    h = __float2bfloat16(x);
    l = __float2bfloat16(x - __bfloat162float(h));
}

// ---------------- combined weight split (single launch) ----------------------
#define N4_QKV (LAYERS*3*DM*DM/4)
#define N4_WO  (LAYERS*DM*DM/4)
#define N4_WG  (LAYERS*FFDIM*DM/4)
#define N4_ALL (N4_QKV + N4_WO + 3*N4_WG)
__global__ void split_all_kernel(
    const float4* __restrict__ wqkv, const float4* __restrict__ wo,
    const float4* __restrict__ wg,   const float4* __restrict__ wu,
    const float4* __restrict__ wd)
{
    int i = blockIdx.x * blockDim.x + threadIdx.x;
    if (i >= N4_ALL) return;
    const float4* src;
    bf162 *hi, *lo;
    int j = i;
    if (j < N4_QKV) {
        src = wqkv; hi = (bf162*)g_wqkv_hi; lo = (bf162*)g_wqkv_lo;
    } else if ((j -= N4_QKV) < N4_WO) {
        src = wo;   hi = (bf162*)g_wo_hi;   lo = (bf162*)g_wo_lo;
    } else if ((j -= N4_WO) < N4_WG) {
        src = wg;   hi = (bf162*)g_wg_hi;   lo = (bf162*)g_wg_lo;
    } else if ((j -= N4_WG) < N4_WG) {
        src = wu;   hi = (bf162*)g_wu_hi;   lo = (bf162*)g_wu_lo;
    } else {
        j -= N4_WG;
        src = wd;   hi = (bf162*)g_wd_hi;   lo = (bf162*)g_wd_lo;
    }
    float4 v = src[j];
    bf16 h0, l0, h1, l1, h2, l2, h3, l3;
    split1(v.x, h0, l0); split1(v.y, h1, l1);
    split1(v.z, h2, l2); split1(v.w, h3, l3);
    bf162 H0; H0.x = h0; H0.y = h1;
    bf162 H1; H1.x = h2; H1.y = h3;
    bf162 L0; L0.x = l0; L0.y = l1;
    bf162 L1; L1.x = l2; L1.y = l3;
    hi[j * 2] = H0; hi[j * 2 + 1] = H1;
    lo[j * 2] = L0; lo[j * 2 + 1] = L1;
}

// ---------------- build x ----------------------------------------------------
__global__ void build_x_kernel(const float* __restrict__ cls_tokens,
                               const float* __restrict__ cls_token,
                               float* __restrict__ x)
{
    int idx = blockIdx.x * blockDim.x + threadIdx.x;
    if (idx >= MTOK * DM) return;
    int row = idx / DM;
    int d   = idx - row * DM;
    int b   = row >> 10;
    int s   = row & (SEQ - 1);
    float v;
    if (s == 0) v = cls_token[d];
    else        v = cls_tokens[((b * (SEQ - 1)) + (s - 1)) * DM + d];
    x[idx] = v;
}

// ---------------- layernorm (fp32 out) ---------------------------------------
__global__ __launch_bounds__(256) void layernorm_kernel(
    const float* __restrict__ in, size_t in_stride, float* __restrict__ out,
    const float* __restrict__ w, const float* __restrict__ b)
{
    int row = blockIdx.x;
    const float* xr = in + (size_t)row * in_stride;
    int t = threadIdx.x;
    float v0 = xr[t], v1 = xr[t + 256], v2 = xr[t + 512];
    float s  = v0 + v1 + v2;
    float sq = v0 * v0 + v1 * v1 + v2 * v2;
    #pragma unroll
    for (int o = 16; o > 0; o >>= 1) {
        s  += __shfl_xor_sync(0xFFFFFFFFu, s,  o);
        sq += __shfl_xor_sync(0xFFFFFFFFu, sq, o);
    }
    __shared__ float ss[8], sqs[8];
    int wid = t >> 5, lane = t & 31;
    if (lane == 0) { ss[wid] = s; sqs[wid] = sq; }
    __syncthreads();
    float ts = 0.f, tq = 0.f;
    #pragma unroll
    for (int i = 0; i < 8; i++) { ts += ss[i]; tq += sqs[i]; }
    float mean = ts * (1.0f / DM);
    float var  = tq * (1.0f / DM) - mean * mean;
    float rstd = rsqrtf(var + 1e-5f);
    float* orow = out + (size_t)row * DM;
    orow[t]       = (v0 - mean) * rstd * w[t]       + b[t];
    orow[t + 256] = (v1 - mean) * rstd * w[t + 256] + b[t + 256];
    orow[t + 512] = (v2 - mean) * rstd * w[t + 512] + b[t + 512];
}

// ---------------- layernorm with fused bf16 hi/lo split ----------------------
__global__ __launch_bounds__(256) void layernorm_split_kernel(
    const float* __restrict__ in, bf16* __restrict__ ohi, bf16* __restrict__ olo,
    const float* __restrict__ w, const float* __restrict__ b)
{
    int row = blockIdx.x;
    const float* xr = in + (size_t)row * DM;
    int t = threadIdx.x;
    float v0 = xr[t], v1 = xr[t + 256], v2 = xr[t + 512];
    float s  = v0 + v1 + v2;
    float sq = v0 * v0 + v1 * v1 + v2 * v2;
    #pragma unroll
    for (int o = 16; o > 0; o >>= 1) {
        s  += __shfl_xor_sync(0xFFFFFFFFu, s,  o);
        sq += __shfl_xor_sync(0xFFFFFFFFu, sq, o);
    }
    __shared__ float ss[8], sqs[8];
    int wid = t >> 5, lane = t & 31;
    if (lane == 0) { ss[wid] = s; sqs[wid] = sq; }
    __syncthreads();
    float ts = 0.f, tq = 0.f;
    #pragma unroll
    for (int i = 0; i < 8; i++) { ts += ss[i]; tq += sqs[i]; }
    float mean = ts * (1.0f / DM);
    float var  = tq * (1.0f / DM) - mean * mean;
    float rstd = rsqrtf(var + 1e-5f);
    size_t base = (size_t)row * DM;
    #pragma unroll
    for (int j = 0; j < 3; j++) {
        float v = (j == 0 ? v0 : (j == 1 ? v1 : v2));
        float y = (v - mean) * rstd * w[t + j * 256] + b[t + j * 256];
        bf16 h, l; split1(y, h, l);
        ohi[base + t + j * 256] = h;
        olo[base + t + j * 256] = l;
    }
}

// ---------------- fused 3-term HMMA bf16 split GEMM (BK=64, 2-stage) ---------
// EPI_MODE: 0 = store fp32
//           1 = add Cin + store fp32
//           2 = split-store bf16 hi/lo
//           3 = silu(Cin)*acc, split-store bf16 hi/lo  (fused FF activation)
#define GSTAGE 65536
#define GEMM_SMEM (2 * GSTAGE)
template <int EPI_MODE>
__global__ __launch_bounds__(256) void mma_gemm_kernel(
    const bf16* __restrict__ Ah, const bf16* __restrict__ Al,
    const bf16* __restrict__ Bh, const bf16* __restrict__ Bl,
    const float* __restrict__ Cin, float* __restrict__ C,
    bf16* __restrict__ Chi, bf16* __restrict__ Clo,
    int M, int N, int K)
{
    extern __shared__ __align__(16) char dynsmem[];
    uint32_t sS = smem_u32(dynsmem);

    int tid = threadIdx.x, wid = tid >> 5, lane = tid & 31;
    int bm = blockIdx.y * 128, bn = blockIdx.x * 128;
    int wm = (wid & 1) * 64;
    int wn = (wid >> 1) * 32;

    float acc[4][4][4];
    #pragma unroll
    for (int i = 0; i < 4; i++)
        #pragma unroll
        for (int j = 0; j < 4; j++)
            #pragma unroll
            for (int q = 0; q < 4; q++) acc[i][j][q] = 0.f;

    const int T = K >> 6;           // stages of 64 k

    int rC = tid >> 1;              // 0..127
    int cC = (tid & 1) * 4;         // 0 or 4 (16B-chunk col)

    auto issue = [&](int t) {
        int k0 = t << 6;
        uint32_t st = sS + (uint32_t)((t & 1) * GSTAGE);
        size_t ao = (size_t)(bm + rC) * K + k0 + cC * 8;
        size_t bo = (size_t)(bn + rC) * K + k0 + cC * 8;
        uint32_t rbase = (uint32_t)(rC * 128);
        #pragma unroll
        for (int i = 0; i < 4; i++) {
            uint32_t sw = rbase + (uint32_t)(((cC + i) ^ (rC & 7)) << 4);
            cp16(st + sw,          Ah + ao + i * 8);
            cp16(st + 16384 + sw,  Al + ao + i * 8);
            cp16(st + 32768 + sw,  Bh + bo + i * 8);
            cp16(st + 49152 + sw,  Bl + bo + i * 8);
        }
        CP_COMMIT();
    };

    issue(0);
    for (int t = 0; t < T; t++) {
        if (t + 1 < T) { issue(t + 1); CP_WAIT1(); }
        else          { CP_WAIT0(); }
        __syncthreads();

        uint32_t st = sS + (uint32_t)((t & 1) * GSTAGE);

        #pragma unroll
        for (int ks = 0; ks < 4; ks++) {
            uint32_t aH[4][4], aL[4][4];
            #pragma unroll
            for (int mt = 0; mt < 4; mt++) {
                int row = wm + mt * 16 + (lane & 15);
                int c = ks * 2 + (lane >> 4);
                uint32_t off = (uint32_t)(row * 128 + ((c ^ (row & 7)) << 4));
                ldsm4(aH[mt][0], aH[mt][1], aH[mt][2], aH[mt][3], st + off);
                ldsm4(aL[mt][0], aL[mt][1], aL[mt][2], aL[mt][3], st + 16384 + off);
            }
            uint32_t bH[4][2], bL[4][2];
            #pragma unroll
            for (int p = 0; p < 2; p++) {
                int n = wn + p * 16 + (lane & 7) + ((lane >> 4) << 3);
                int c = ks * 2 + ((lane >> 3) & 1);
                uint32_t off = (uint32_t)(n * 128 + ((c ^ (n & 7)) << 4));
                ldsm4(bH[2 * p][0], bH[2 * p][1], bH[2 * p + 1][0], bH[2 * p + 1][1],
                      st + 32768 + off);
                ldsm4(bL[2 * p][0], bL[2 * p][1], bL[2 * p + 1][0], bL[2 * p + 1][1],
                      st + 49152 + off);
            }
            #pragma unroll
            for (int mt = 0; mt < 4; mt++)
                #pragma unroll
                for (int nt = 0; nt < 4; nt++) {
                    mma16816(acc[mt][nt], aH[mt], bH[nt]);
                    mma16816(acc[mt][nt], aH[mt], bL[nt]);
                    mma16816(acc[mt][nt], aL[mt], bH[nt]);
                }
        }
        __syncthreads();
    }

    int grp = lane >> 2, tig = lane & 3;
    #pragma unroll
    for (int mt = 0; mt < 4; mt++) {
        #pragma unroll
        for (int nt = 0; nt < 4; nt++) {
            int row = bm + wm + mt * 16 + grp;
            int col = bn + wn + nt * 8 + tig * 2;
            size_t o0 = (size_t)row * N + col;
            size_t o1 = (size_t)(row + 8) * N + col;
            float2 v0, v1;
            v0.x = acc[mt][nt][0]; v0.y = acc[mt][nt][1];
            v1.x = acc[mt][nt][2]; v1.y = acc[mt][nt][3];
            if (EPI_MODE == 1) {
                float2 c0 = *(const float2*)&Cin[o0];
                float2 c1 = *(const float2*)&Cin[o1];
                v0.x += c0.x; v0.y += c0.y;
                v1.x += c1.x; v1.y += c1.y;
            }
            if (EPI_MODE == 3) {
                // acc = up tile; Cin = gate tile; y = silu(gate)*up
                float2 g0 = *(const float2*)&Cin[o0];
                float2 g1 = *(const float2*)&Cin[o1];
                v0.x = v0.x * g0.x / (1.0f + __expf(-g0.x));
                v0.y = v0.y * g0.y / (1.0f + __expf(-g0.y));
                v1.x = v1.x * g1.x / (1.0f + __expf(-g1.x));
                v1.y = v1.y * g1.y / (1.0f + __expf(-g1.y));
            }
            if (EPI_MODE == 2 || EPI_MODE == 3) {
                bf16 h0, l0, h1, l1;
                split1(v0.x, h0, l0); split1(v0.y, h1, l1);
                bf162 H0; H0.x = h0; H0.y = h1;
                bf162 L0; L0.x = l0; L0.y = l1;
                *(bf162*)(Chi + o0) = H0;
                *(bf162*)(Clo + o0) = L0;
                split1(v1.x, h0, l0); split1(v1.y, h1, l1);
                bf162 H1; H1.x = h0; H1.y = h1;
                bf162 L1; L1.x = l0; L1.y = l1;
                *(bf162*)(Chi + o1) = H1;
                *(bf162*)(Clo + o1) = L1;
            } else {
                *(float2*)&C[o0] = v0;
                *(float2*)&C[o1] = v1;
            }
        }
    }
}

// ---------------- HMMA flash attention (split bf16, ALiBi) -------------------
#define ATT_SMEM 65536
__global__ __launch_bounds__(128) void flash_attn_mma_kernel(
    const bf16* __restrict__ qkh, const bf16* __restrict__ qkl,
    const float* __restrict__ log_slopes,
    bf16* __restrict__ out_hi, bf16* __restrict__ out_lo)
{
    extern __shared__ __align__(16) char asmem[];
    uint32_t sb = smem_u32(asmem);
    const int QW = 3 * DM;
    int qt = blockIdx.x, hh = blockIdx.y, b = blockIdx.z;
    int tid = threadIdx.x, wid = tid >> 5, lane = tid & 31;
    int wm = wid * 32;
    int grp = lane >> 2, tig = lane & 3;
    float slope = __expf(log_slopes[hh]);
    const float scale = 0.14433756729740643f;  // 1/sqrt(48)
    size_t rbase = (size_t)(b * SEQ + qt * 128);

    #pragma unroll
    for (int i = 0; i < 6; i++) {
        int j = i * 128 + tid;
        int r = j / 6, c = j - r * 6;
        uint32_t dst = (uint32_t)(r * 128 + ((c ^ (r & 3)) << 4));
        size_t g = (rbase + r) * QW + hh * HDIM + c * 8;
        cp16(sb + dst, qkh + g);
        cp16(sb + 16384 + dst, qkl + g);
    }
    CP_COMMIT(); CP_WAIT0();
    __syncthreads();

    uint32_t qfh[2][3][4], qfl[2][3][4];
    #pragma unroll
    for (int mt = 0; mt < 2; mt++)
        #pragma unroll
        for (int ks = 0; ks < 3; ks++) {
            int r = wm + mt * 16 + (lane & 15);
            int c = ks * 2 + (lane >> 4);
            uint32_t off = (uint32_t)(r * 128 + ((c ^ (r & 3)) << 4));
            ldsm4(qfh[mt][ks][0], qfh[mt][ks][1], qfh[mt][ks][2], qfh[mt][ks][3],
                  sb + off);
            ldsm4(qfl[mt][ks][0], qfl[mt][ks][1], qfl[mt][ks][2], qfl[mt][ks][3],
                  sb + 16384 + off);
        }
    __syncthreads();

    float oacc[2][6][4];
    #pragma unroll
    for (int mt = 0; mt < 2; mt++)
        #pragma unroll
        for (int nt = 0; nt < 6; nt++)
            #pragma unroll
            for (int q = 0; q < 4; q++) oacc[mt][nt][q] = 0.f;
    float m_run[4], l_run[4];
    #pragma unroll
    for (int rr = 0; rr < 4; rr++) { m_run[rr] = -INFINITY; l_run[rr] = 0.f; }

    auto issueKV = [&](int kt) {
        uint32_t st = sb + (uint32_t)((kt & 1) * 32768);
        #pragma unroll
        for (int i = 0; i < 12; i++) {
            int j = i * 128 + tid;
            int mat = j / 384;
            int rem = j - mat * 384;
            int rr = rem / 6;
            int cc = rem - rr * 6;
            uint32_t dst = st + (uint32_t)(mat * 8192)
                         + (uint32_t)(rr * 128 + ((cc ^ (rr & 3)) << 4));
            size_t g = (size_t)(b * SEQ + kt * 64 + rr) * QW + hh * HDIM
                     + ((mat < 2) ? DM : 2 * DM) + cc * 8;
            const bf16* src = (mat & 1) ? qkl : qkh;
            cp16(dst, src + g);
        }
        CP_COMMIT();
    };

    issueKV(0);
    for (int kt = 0; kt < SEQ / 64; kt++) {
        if (kt + 1 < SEQ / 64) { issueKV(kt + 1); CP_WAIT1(); }
        else                   { CP_WAIT0(); }
        __syncthreads();
        uint32_t st = sb + (uint32_t)((kt & 1) * 32768);

        float s[2][8][4];
        #pragma unroll
        for (int mt = 0; mt < 2; mt++)
            #pragma unroll
            for (int nt = 0; nt < 8; nt++)
                #pragma unroll
                for (int q = 0; q < 4; q++) s[mt][nt][q] = 0.f;

        #pragma unroll
        for (int ks = 0; ks < 3; ks++) {
            uint32_t bh[8][2], bl[8][2];
            #pragma unroll
            for (int p = 0; p < 4; p++) {
                int n = p * 16 + (lane & 7) + ((lane >> 4) << 3);
                int c = ks * 2 + ((lane >> 3) & 1);
                uint32_t off = (uint32_t)(n * 128 + ((c ^ (n & 3)) << 4));
                ldsm4(bh[2*p][0], bh[2*p][1], bh[2*p+1][0], bh[2*p+1][1], st + off);
                ldsm4(bl[2*p][0], bl[2*p][1], bl[2*p+1][0], bl[2*p+1][1], st + 8192 + off);
            }
            #pragma unroll
            for (int mt = 0; mt < 2; mt++)
                #pragma unroll
                for (int nt = 0; nt < 8; nt++) {
                    mma16816(s[mt][nt], qfh[mt][ks], bh[nt]);
                    mma16816(s[mt][nt], qfh[mt][ks], bl[nt]);
                    mma16816(s[mt][nt], qfl[mt][ks], bh[nt]);
                }
        }

        float corr[4];
        #pragma unroll
        for (int rr = 0; rr < 4; rr++) {
            int mt = rr >> 1, half = rr & 1;
            int qrow = qt * 128 + wm + mt * 16 + half * 8 + grp;
            float mx = -INFINITY;
            #pragma unroll
            for (int nt = 0; nt < 8; nt++)
                #pragma unroll
                for (int jx = 0; jx < 2; jx++) {
                    int c = half * 2 + jx;
                    int kcol = kt * 64 + nt * 8 + tig * 2 + jx;
                    float v = s[mt][nt][c] * scale
                              - slope * fabsf((float)(qrow - kcol));
                    s[mt][nt][c] = v;
                    mx = fmaxf(mx, v);
                }
            mx = fmaxf(mx, __shfl_xor_sync(0xFFFFFFFFu, mx, 1));
            mx = fmaxf(mx, __shfl_xor_sync(0xFFFFFFFFu, mx, 2));
            float newm = fmaxf(m_run[rr], mx);
            corr[rr] = __expf(m_run[rr] - newm);
            m_run[rr] = newm;
            float ps = 0.f;
            #pragma unroll
            for (int nt = 0; nt < 8; nt++)
                #pragma unroll
                for (int jx = 0; jx < 2; jx++) {
                    int c = half * 2 + jx;
                    float p = __expf(s[mt][nt][c] - newm);
                    s[mt][nt][c] = p;
                    ps += p;
                }
            ps += __shfl_xor_sync(0xFFFFFFFFu, ps, 1);
            ps += __shfl_xor_sync(0xFFFFFFFFu, ps, 2);
            l_run[rr] = l_run[rr] * corr[rr] + ps;
        }
        #pragma unroll
        for (int mt = 0; mt < 2; mt++)
            #pragma unroll
            for (int nt = 0; nt < 6; nt++) {
                oacc[mt][nt][0] *= corr[mt*2];     oacc[mt][nt][1] *= corr[mt*2];
                oacc[mt][nt][2] *= corr[mt*2 + 1]; oacc[mt][nt][3] *= corr[mt*2 + 1];
            }

        #pragma unroll
        for (int ks2 = 0; ks2 < 4; ks2++) {
            uint32_t pah[2][4], pal[2][4];
            #pragma unroll
            for (int mt = 0; mt < 2; mt++)
                #pragma unroll
                for (int q2 = 0; q2 < 4; q2++) {
                    int nt = 2 * ks2 + (q2 >> 1);
                    int cb = (q2 & 1) * 2;
                    float v0 = s[mt][nt][cb], v1 = s[mt][nt][cb + 1];
                    bf162 H = __floats2bfloat162_rn(v0, v1);
                    float h0 = __bfloat162float(H.x), h1 = __bfloat162float(H.y);
                    bf162 L = __floats2bfloat162_rn(v0 - h0, v1 - h1);
                    pah[mt][q2] = *(uint32_t*)&H;
                    pal[mt][q2] = *(uint32_t*)&L;
                }
            uint32_t vh[6][2], vl[6][2];
            #pragma unroll
            for (int vt = 0; vt < 3; vt++) {
                int r = ks2 * 16 + (lane & 15);
                int c = vt * 2 + (lane >> 4);
                uint32_t off = (uint32_t)(r * 128 + ((c ^ (r & 3)) << 4));
                ldsm4t(vh[2*vt][0], vh[2*vt][1], vh[2*vt+1][0], vh[2*vt+1][1],
                       st + 16384 + off);
                ldsm4t(vl[2*vt][0], vl[2*vt][1], vl[2*vt+1][0], vl[2*vt+1][1],
                       st + 24576 + off);
            }
            #pragma unroll
            for (int mt = 0; mt < 2; mt++)
                #pragma unroll
                for (int nt = 0; nt < 6; nt++) {
                    mma16816(oacc[mt][nt], pah[mt], vh[nt]);
                    mma16816(oacc[mt][nt], pah[mt], vl[nt]);
                    mma16816(oacc[mt][nt], pal[mt], vh[nt]);
                }
        }
        __syncthreads();
    }

    #pragma unroll
    for (int mt = 0; mt < 2; mt++) {
        float inv0 = 1.0f / l_run[mt*2];
        float inv1 = 1.0f / l_run[mt*2 + 1];
        size_t row0 = (rbase + wm + mt * 16 + grp) * DM + hh * HDIM + tig * 2;
        size_t row1 = row0 + 8 * DM;
        #pragma unroll
        for (int nt = 0; nt < 6; nt++) {
            float v00 = oacc[mt][nt][0] * inv0, v01 = oacc[mt][nt][1] * inv0;
            float v10 = oacc[mt][nt][2] * inv1, v11 = oacc[mt][nt][3] * inv1;
            bf16 h0, l0, h1, l1;
            split1(v00, h0, l0); split1(v01, h1, l1);
            bf162 H0; H0.x = h0; H0.y = h1;
            bf162 L0; L0.x = l0; L0.y = l1;
            *(bf162*)(out_hi + row0 + nt * 8) = H0;
            *(bf162*)(out_lo + row0 + nt * 8) = L0;
            split1(v10, h0, l0); split1(v11, h1, l1);
            bf162 H1; H1.x = h0; H1.y = h1;
            bf162 L1; L1.x = l0; L1.y = l1;
            *(bf162*)(out_hi + row1 + nt * 8) = H1;
            *(bf162*)(out_lo + row1 + nt * 8) = L1;
        }
    }
}

// ---------------- host orchestration ----------------------------------------
static void run_gemm(int mode, const bf16* ah, const bf16* al,
                     const bf16* bh, const bf16* bl,
                     const float* cin, float* c, bf16* chi, bf16* clo,
                     int M, int N, int K)
{
    dim3 grid(N / 128, M / 128);
    if (mode == 0)
        mma_gemm_kernel<0><<<grid, 256, GEMM_SMEM>>>(ah, al, bh, bl, cin, c,
                                                     chi, clo, M, N, K);
    else if (mode == 1)
        mma_gemm_kernel<1><<<grid, 256, GEMM_SMEM>>>(ah, al, bh, bl, cin, c,
                                                     chi, clo, M, N, K);
    else if (mode == 2)
        mma_gemm_kernel<2><<<grid, 256, GEMM_SMEM>>>(ah, al, bh, bl, cin, c,
                                                     chi, clo, M, N, K);
    else
        mma_gemm_kernel<3><<<grid, 256, GEMM_SMEM>>>(ah, al, bh, bl, cin, c,
                                                     chi, clo, M, N, K);
}

extern "C" void kernel_launch(void* const* d_in, const int* in_sizes, int n_in,
                              void* d_out, int out_size)
{
    const float* cls_tokens = (const float*)d_in[0];
    const float* cls_token  = (const float*)d_in[1];
    const float* log_slopes = (const float*)d_in[2];
    const float* Wqkv       = (const float*)d_in[3];
    const float* Wo         = (const float*)d_in[4];
    const float* Wg         = (const float*)d_in[5];
    const float* Wu         = (const float*)d_in[6];
    const float* Wd         = (const float*)d_in[7];
    const float* ln1w       = (const float*)d_in[8];
    const float* ln1b       = (const float*)d_in[9];
    const float* ln2w       = (const float*)d_in[10];
    const float* ln2b       = (const float*)d_in[11];
    const float* finw       = (const float*)d_in[12];
    const float* finb       = (const float*)d_in[13];
    float* out = (float*)d_out;

    cudaFuncSetAttribute(mma_gemm_kernel<0>,
                         cudaFuncAttributeMaxDynamicSharedMemorySize, GEMM_SMEM);
    cudaFuncSetAttribute(mma_gemm_kernel<1>,
                         cudaFuncAttributeMaxDynamicSharedMemorySize, GEMM_SMEM);
    cudaFuncSetAttribute(mma_gemm_kernel<2>,
                         cudaFuncAttributeMaxDynamicSharedMemorySize, GEMM_SMEM);
    cudaFuncSetAttribute(mma_gemm_kernel<3>,
                         cudaFuncAttributeMaxDynamicSharedMemorySize, GEMM_SMEM);
    cudaFuncSetAttribute(flash_attn_mma_kernel,
                         cudaFuncAttributeMaxDynamicSharedMemorySize, ATT_SMEM);

    float *x, *gate;
    bf16 *qkvh, *qkvl;
    bf16 *h_hi, *h_lo, *at_hi, *at_lo, *gg_hi, *gg_lo;
    bf16 *wqkv_hi, *wqkv_lo, *wo_hi, *wo_lo, *wg_hi, *wg_lo,
         *wu_hi, *wu_lo, *wd_hi, *wd_lo;
    cudaGetSymbolAddress((void**)&x,    g_x);
    cudaGetSymbolAddress((void**)&gate, g_gate);
    cudaGetSymbolAddress((void**)&qkvh, g_qkvh);
    cudaGetSymbolAddress((void**)&qkvl, g_qkvl);
    cudaGetSymbolAddress((void**)&h_hi, g_h_hi);
    cudaGetSymbolAddress((void**)&h_lo, g_h_lo);
    cudaGetSymbolAddress((void**)&at_hi, g_at_hi);
    cudaGetSymbolAddress((void**)&at_lo, g_at_lo);
    cudaGetSymbolAddress((void**)&gg_hi, g_g_hi);
    cudaGetSymbolAddress((void**)&gg_lo, g_g_lo);
    cudaGetSymbolAddress((void**)&wqkv_hi, g_wqkv_hi);
    cudaGetSymbolAddress((void**)&wqkv_lo, g_wqkv_lo);
    cudaGetSymbolAddress((void**)&wo_hi, g_wo_hi);
    cudaGetSymbolAddress((void**)&wo_lo, g_wo_lo);
    cudaGetSymbolAddress((void**)&wg_hi, g_wg_hi);
    cudaGetSymbolAddress((void**)&wg_lo, g_wg_lo);
    cudaGetSymbolAddress((void**)&wu_hi, g_wu_hi);
    cudaGetSymbolAddress((void**)&wu_lo, g_wu_lo);
    cudaGetSymbolAddress((void**)&wd_hi, g_wd_hi);
    cudaGetSymbolAddress((void**)&wd_lo, g_wd_lo);

    // single combined weight split (also shifts ncu -s 5 capture onto a GEMM)
    split_all_kernel<<<(N4_ALL + 255) / 256, 256>>>(
        (const float4*)Wqkv, (const float4*)Wo, (const float4*)Wg,
        (const float4*)Wu, (const float4*)Wd);

    build_x_kernel<<<(MTOK * DM + 255) / 256, 256>>>(cls_tokens, cls_token, x);

    for (int l = 0; l < LAYERS; l++) {
        size_t oq = (size_t)l * 3 * DM * DM;
        size_t oo = (size_t)l * DM * DM;
        size_t og = (size_t)l * FFDIM * DM;
        size_t od = (size_t)l * DM * FFDIM;

        layernorm_split_kernel<<<MTOK, 256>>>(x, h_hi, h_lo,
                                              ln1w + l * DM, ln1b + l * DM);

        run_gemm(2, h_hi, h_lo, wqkv_hi + oq, wqkv_lo + oq,
                 nullptr, nullptr, qkvh, qkvl, MTOK, 3 * DM, DM);

        flash_attn_mma_kernel<<<dim3(SEQ / 128, NH, BATCH), 128, ATT_SMEM>>>(
            qkvh, qkvl, log_slopes, at_hi, at_lo);

        run_gemm(1, at_hi, at_lo, wo_hi + oo, wo_lo + oo,
                 x, x, nullptr, nullptr, MTOK, DM, DM);

        layernorm_split_kernel<<<MTOK, 256>>>(x, h_hi, h_lo,
                                              ln2w + l * DM, ln2b + l * DM);

        // gate GEMM -> fp32
        run_gemm(0, h_hi, h_lo, wg_hi + og, wg_lo + og,
                 nullptr, gate, nullptr, nullptr, MTOK, FFDIM, DM);
        // up GEMM with fused silu(gate)*up + bf16 split epilogue
        run_gemm(3, h_hi, h_lo, wu_hi + og, wu_lo + og,
                 gate, nullptr, gg_hi, gg_lo, MTOK, FFDIM, DM);

        run_gemm(1, gg_hi, gg_lo, wd_hi + od, wd_lo + od,
                 x, x, nullptr, nullptr, MTOK, DM, FFDIM);
    }

    layernorm_kernel<<<BATCH, 256>>>(x, (size_t)SEQ * DM, out, finw, finb);
}

// round 16
// speedup vs baseline: 1.0056x; 1.0056x over previous
#include <cuda_runtime.h>
#include <cuda_bf16.h>
#include <math.h>
#include <stdint.h>
#include <string.h>

// ---------------- problem constants ----------------
#define LAYERS 6
#define BATCH  4
#define SEQ    1024
#define DM     768
#define NH     16
#define HDIM   48
#define FFDIM  3072
#define MTOK   (BATCH*SEQ)   // 4096

typedef unsigned long long u64;
typedef __nv_bfloat16  bf16;
typedef __nv_bfloat162 bf162;

// ---------------- mma.sync / ldmatrix / cp.async helpers --------------------
__device__ __forceinline__ uint32_t smem_u32(const void* p) {
    uint32_t a;
    asm("{ .reg .u64 t; cvta.to.shared.u64 t, %1; cvt.u32.u64 %0, t; }"
        : "=r"(a) : "l"(p));
    return a;
}
__device__ __forceinline__ void cp16(uint32_t dst, const void* src) {
    asm volatile("cp.async.cg.shared.global [%0], [%1], 16;" :: "r"(dst), "l"(src));
}
#define CP_COMMIT() asm volatile("cp.async.commit_group;" ::: "memory")
#define CP_WAIT1()  asm volatile("cp.async.wait_group 1;" ::: "memory")
#define CP_WAIT0()  asm volatile("cp.async.wait_group 0;" ::: "memory")

__device__ __forceinline__ void ldsm4(uint32_t &r0, uint32_t &r1,
                                      uint32_t &r2, uint32_t &r3, uint32_t addr) {
    asm volatile("ldmatrix.sync.aligned.m8n8.x4.shared.b16 {%0,%1,%2,%3}, [%4];"
                 : "=r"(r0), "=r"(r1), "=r"(r2), "=r"(r3) : "r"(addr));
}
__device__ __forceinline__ void ldsm4t(uint32_t &r0, uint32_t &r1,
                                       uint32_t &r2, uint32_t &r3, uint32_t addr) {
    asm volatile("ldmatrix.sync.aligned.m8n8.x4.trans.shared.b16 {%0,%1,%2,%3}, [%4];"
                 : "=r"(r0), "=r"(r1), "=r"(r2), "=r"(r3) : "r"(addr));
}
__device__ __forceinline__ void mma16816(float* d, const uint32_t* a,
                                         const uint32_t* b) {
    asm volatile("mma.sync.aligned.m16n8k16.row.col.f32.bf16.bf16.f32 "
        "{%0,%1,%2,%3}, {%4,%5,%6,%7}, {%8,%9}, {%0,%1,%2,%3};"
        : "+f"(d[0]), "+f"(d[1]), "+f"(d[2]), "+f"(d[3])
        : "r"(a[0]), "r"(a[1]), "r"(a[2]), "r"(a[3]), "r"(b[0]), "r"(b[1]));
}

// ---------------- scratch (device globals) ----------------------------------
__device__ __align__(16) float g_x   [MTOK*DM];
__device__ __align__(16) float g_gate[MTOK*FFDIM];
__device__ __align__(16) float g_up  [MTOK*FFDIM];

__device__ __align__(16) bf16 g_qkvh[MTOK*3*DM];
__device__ __align__(16) bf16 g_qkvl[MTOK*3*DM];

__device__ __align__(16) bf16 g_h_hi [MTOK*DM];
__device__ __align__(16) bf16 g_h_lo [MTOK*DM];
__device__ __align__(16) bf16 g_at_hi[MTOK*DM];
__device__ __align__(16) bf16 g_at_lo[MTOK*DM];
__device__ __align__(16) bf16 g_g_hi [MTOK*FFDIM];
__device__ __align__(16) bf16 g_g_lo [MTOK*FFDIM];

__device__ __align__(16) bf16 g_wqkv_hi[LAYERS*3*DM*DM];
__device__ __align__(16) bf16 g_wqkv_lo[LAYERS*3*DM*DM];
__device__ __align__(16) bf16 g_wo_hi  [LAYERS*DM*DM];
__device__ __align__(16) bf16 g_wo_lo  [LAYERS*DM*DM];
__device__ __align__(16) bf16 g_wg_hi  [LAYERS*FFDIM*DM];
__device__ __align__(16) bf16 g_wg_lo  [LAYERS*FFDIM*DM];
__device__ __align__(16) bf16 g_wu_hi  [LAYERS*FFDIM*DM];
__device__ __align__(16) bf16 g_wu_lo  [LAYERS*FFDIM*DM];
__device__ __align__(16) bf16 g_wd_hi  [LAYERS*DM*FFDIM];
__device__ __align__(16) bf16 g_wd_lo  [LAYERS*DM*FFDIM];

// ---------------- split helpers ---------------------------------------------
__device__ __forceinline__ void split1(float x, bf16 &h, bf16 &l) {
    h = __float2bfloat16(x);
    l = __float2bfloat16(x - __bfloat162float(h));
}

// ---------------- combined weight split (single launch) ----------------------
#define N4_QKV (LAYERS*3*DM*DM/4)
#define N4_WO  (LAYERS*DM*DM/4)
#define N4_WG  (LAYERS*FFDIM*DM/4)
#define N4_ALL (N4_QKV + N4_WO + 3*N4_WG)
__global__ void split_all_kernel(
    const float4* __restrict__ wqkv, const float4* __restrict__ wo,
    const float4* __restrict__ wg,   const float4* __restrict__ wu,
    const float4* __restrict__ wd)
{
    int i = blockIdx.x * blockDim.x + threadIdx.x;
    if (i >= N4_ALL) return;
    const float4* src;
    bf162 *hi, *lo;
    int j = i;
    if (j < N4_QKV) {
        src = wqkv; hi = (bf162*)g_wqkv_hi; lo = (bf162*)g_wqkv_lo;
    } else if ((j -= N4_QKV) < N4_WO) {
        src = wo;   hi = (bf162*)g_wo_hi;   lo = (bf162*)g_wo_lo;
    } else if ((j -= N4_WO) < N4_WG) {
        src = wg;   hi = (bf162*)g_wg_hi;   lo = (bf162*)g_wg_lo;
    } else if ((j -= N4_WG) < N4_WG) {
        src = wu;   hi = (bf162*)g_wu_hi;   lo = (bf162*)g_wu_lo;
    } else {
        j -= N4_WG;
        src = wd;   hi = (bf162*)g_wd_hi;   lo = (bf162*)g_wd_lo;
    }
    float4 v = src[j];
    bf16 h0, l0, h1, l1, h2, l2, h3, l3;
    split1(v.x, h0, l0); split1(v.y, h1, l1);
    split1(v.z, h2, l2); split1(v.w, h3, l3);
    bf162 H0; H0.x = h0; H0.y = h1;
    bf162 H1; H1.x = h2; H1.y = h3;
    bf162 L0; L0.x = l0; L0.y = l1;
    bf162 L1; L1.x = l2; L1.y = l3;
    hi[j * 2] = H0; hi[j * 2 + 1] = H1;
    lo[j * 2] = L0; lo[j * 2 + 1] = L1;
}

// ---------------- build x ----------------------------------------------------
__global__ void build_x_kernel(const float* __restrict__ cls_tokens,
                               const float* __restrict__ cls_token,
                               float* __restrict__ x)
{
    int idx = blockIdx.x * blockDim.x + threadIdx.x;
    if (idx >= MTOK * DM) return;
    int row = idx / DM;
    int d   = idx - row * DM;
    int b   = row >> 10;
    int s   = row & (SEQ - 1);
    float v;
    if (s == 0) v = cls_token[d];
    else        v = cls_tokens[((b * (SEQ - 1)) + (s - 1)) * DM + d];
    x[idx] = v;
}

// ---------------- layernorm (fp32 out) ---------------------------------------
__global__ __launch_bounds__(256) void layernorm_kernel(
    const float* __restrict__ in, size_t in_stride, float* __restrict__ out,
    const float* __restrict__ w, const float* __restrict__ b)
{
    int row = blockIdx.x;
    const float* xr = in + (size_t)row * in_stride;
    int t = threadIdx.x;
    float v0 = xr[t], v1 = xr[t + 256], v2 = xr[t + 512];
    float s  = v0 + v1 + v2;
    float sq = v0 * v0 + v1 * v1 + v2 * v2;
    #pragma unroll
    for (int o = 16; o > 0; o >>= 1) {
        s  += __shfl_xor_sync(0xFFFFFFFFu, s,  o);
        sq += __shfl_xor_sync(0xFFFFFFFFu, sq, o);
    }
    __shared__ float ss[8], sqs[8];
    int wid = t >> 5, lane = t & 31;
    if (lane == 0) { ss[wid] = s; sqs[wid] = sq; }
    __syncthreads();
    float ts = 0.f, tq = 0.f;
    #pragma unroll
    for (int i = 0; i < 8; i++) { ts += ss[i]; tq += sqs[i]; }
    float mean = ts * (1.0f / DM);
    float var  = tq * (1.0f / DM) - mean * mean;
    float rstd = rsqrtf(var + 1e-5f);
    float* orow = out + (size_t)row * DM;
    orow[t]       = (v0 - mean) * rstd * w[t]       + b[t];
    orow[t + 256] = (v1 - mean) * rstd * w[t + 256] + b[t + 256];
    orow[t + 512] = (v2 - mean) * rstd * w[t + 512] + b[t + 512];
}

// ---------------- layernorm with fused bf16 hi/lo split ----------------------
__global__ __launch_bounds__(256) void layernorm_split_kernel(
    const float* __restrict__ in, bf16* __restrict__ ohi, bf16* __restrict__ olo,
    const float* __restrict__ w, const float* __restrict__ b)
{
    int row = blockIdx.x;
    const float* xr = in + (size_t)row * DM;
    int t = threadIdx.x;
    float v0 = xr[t], v1 = xr[t + 256], v2 = xr[t + 512];
    float s  = v0 + v1 + v2;
    float sq = v0 * v0 + v1 * v1 + v2 * v2;
    #pragma unroll
    for (int o = 16; o > 0; o >>= 1) {
        s  += __shfl_xor_sync(0xFFFFFFFFu, s,  o);
        sq += __shfl_xor_sync(0xFFFFFFFFu, sq, o);
    }
    __shared__ float ss[8], sqs[8];
    int wid = t >> 5, lane = t & 31;
    if (lane == 0) { ss[wid] = s; sqs[wid] = sq; }
    __syncthreads();
    float ts = 0.f, tq = 0.f;
    #pragma unroll
    for (int i = 0; i < 8; i++) { ts += ss[i]; tq += sqs[i]; }
    float mean = ts * (1.0f / DM);
    float var  = tq * (1.0f / DM) - mean * mean;
    float rstd = rsqrtf(var + 1e-5f);
    size_t base = (size_t)row * DM;
    #pragma unroll
    for (int j = 0; j < 3; j++) {
        float v = (j == 0 ? v0 : (j == 1 ? v1 : v2));
        float y = (v - mean) * rstd * w[t + j * 256] + b[t + j * 256];
        bf16 h, l; split1(y, h, l);
        ohi[base + t + j * 256] = h;
        olo[base + t + j * 256] = l;
    }
}

// ---------------- fused 3-term HMMA bf16 split GEMM (BK=32, 2-stage, 2 CTA/SM)
// EPI_MODE: 0 = store fp32, 1 = add Cin + store fp32, 2 = split-store bf16 hi/lo
// Stage = 4 tiles (Ah,Al,Bh,Bl) of 128x32 bf16 (8KB each) -> 32KB/stage,
// 64KB/CTA total; __launch_bounds__(256,2) caps regs at 128 so TWO CTAs
// co-reside per SM (2*64KB smem, 2*32K regs) to fill the tensor-pipe gaps
// seen in the R15 profile (tensor=47.7%, occ=12.4%).
#define GSTAGE 32768
#define GEMM_SMEM (2 * GSTAGE)
template <int EPI_MODE>
__global__ __launch_bounds__(256, 2) void mma_gemm_kernel(
    const bf16* __restrict__ Ah, const bf16* __restrict__ Al,
    const bf16* __restrict__ Bh, const bf16* __restrict__ Bl,
    const float* __restrict__ Cin, float* __restrict__ C,
    bf16* __restrict__ Chi, bf16* __restrict__ Clo,
    int M, int N, int K)
{
    extern __shared__ __align__(16) char dynsmem[];
    uint32_t sS = smem_u32(dynsmem);

    int tid = threadIdx.x, wid = tid >> 5, lane = tid & 31;
    int bm = blockIdx.y * 128, bn = blockIdx.x * 128;
    int wm = (wid & 1) * 64;
    int wn = (wid >> 1) * 32;

    float acc[4][4][4];
    #pragma unroll
    for (int i = 0; i < 4; i++)
        #pragma unroll
        for (int j = 0; j < 4; j++)
            #pragma unroll
            for (int q = 0; q < 4; q++) acc[i][j][q] = 0.f;

    const int T = K >> 5;

    int r0c = (tid * 2) >> 2;
    int c0c = (tid * 2) & 3;
    int r1c = (tid * 2 + 1) >> 2;
    int c1c = (tid * 2 + 1) & 3;
    uint32_t swA0 = (uint32_t)(r0c * 64 + ((c0c ^ (r0c & 3)) << 4));
    uint32_t swA1 = (uint32_t)(r1c * 64 + ((c1c ^ (r1c & 3)) << 4));

    auto issue = [&](int t) {
        int k0 = t << 5;
        uint32_t st = sS + (uint32_t)((t & 1) * GSTAGE);
        size_t a0 = (size_t)(bm + r0c) * K + k0;
        size_t a1 = (size_t)(bm + r1c) * K + k0;
        size_t b0 = (size_t)(bn + r0c) * K + k0;
        size_t b1 = (size_t)(bn + r1c) * K + k0;
        cp16(st + 0     + swA0, Ah + a0 + c0c * 8);
        cp16(st + 0     + swA1, Ah + a1 + c1c * 8);
        cp16(st + 8192  + swA0, Al + a0 + c0c * 8);
        cp16(st + 8192  + swA1, Al + a1 + c1c * 8);
        cp16(st + 16384 + swA0, Bh + b0 + c0c * 8);
        cp16(st + 16384 + swA1, Bh + b1 + c1c * 8);
        cp16(st + 24576 + swA0, Bl + b0 + c0c * 8);
        cp16(st + 24576 + swA1, Bl + b1 + c1c * 8);
        CP_COMMIT();
    };

    issue(0);
    for (int t = 0; t < T; t++) {
        if (t + 1 < T) { issue(t + 1); CP_WAIT1(); }
        else          { CP_WAIT0(); }
        __syncthreads();

        uint32_t st = sS + (uint32_t)((t & 1) * GSTAGE);

        #pragma unroll
        for (int ks = 0; ks < 2; ks++) {
            uint32_t aH[4][4], aL[4][4];
            #pragma unroll
            for (int mt = 0; mt < 4; mt++) {
                int row = wm + mt * 16 + (lane & 15);
                int c = (ks * 16 + ((lane >> 4) << 3)) >> 3;
                uint32_t off = (uint32_t)(row * 64 + ((c ^ (row & 3)) << 4));
                ldsm4(aH[mt][0], aH[mt][1], aH[mt][2], aH[mt][3], st + off);
                ldsm4(aL[mt][0], aL[mt][1], aL[mt][2], aL[mt][3], st + 8192 + off);
            }
            uint32_t bH[4][2], bL[4][2];
            #pragma unroll
            for (int p = 0; p < 2; p++) {
                int n = wn + p * 16 + (lane & 7) + ((lane >> 4) << 3);
                int c = (ks * 16 + (((lane >> 3) & 1) << 3)) >> 3;
                uint32_t off = (uint32_t)(n * 64 + ((c ^ (n & 3)) << 4));
                ldsm4(bH[2 * p][0], bH[2 * p][1], bH[2 * p + 1][0], bH[2 * p + 1][1],
                      st + 16384 + off);
                ldsm4(bL[2 * p][0], bL[2 * p][1], bL[2 * p + 1][0], bL[2 * p + 1][1],
                      st + 24576 + off);
            }
            #pragma unroll
            for (int mt = 0; mt < 4; mt++)
                #pragma unroll
                for (int nt = 0; nt < 4; nt++) {
                    mma16816(acc[mt][nt], aH[mt], bH[nt]);
                    mma16816(acc[mt][nt], aH[mt], bL[nt]);
                    mma16816(acc[mt][nt], aL[mt], bH[nt]);
                }
        }
        __syncthreads();
    }

    int grp = lane >> 2, tig = lane & 3;
    #pragma unroll
    for (int mt = 0; mt < 4; mt++) {
        #pragma unroll
        for (int nt = 0; nt < 4; nt++) {
            int row = bm + wm + mt * 16 + grp;
            int col = bn + wn + nt * 8 + tig * 2;
            size_t o0 = (size_t)row * N + col;
            size_t o1 = (size_t)(row + 8) * N + col;
            float2 v0, v1;
            v0.x = acc[mt][nt][0]; v0.y = acc[mt][nt][1];
            v1.x = acc[mt][nt][2]; v1.y = acc[mt][nt][3];
            if (EPI_MODE == 1) {
                float2 c0 = *(const float2*)&Cin[o0];
                float2 c1 = *(const float2*)&Cin[o1];
                v0.x += c0.x; v0.y += c0.y;
                v1.x += c1.x; v1.y += c1.y;
            }
            if (EPI_MODE == 2) {
                bf16 h0, l0, h1, l1;
                split1(v0.x, h0, l0); split1(v0.y, h1, l1);
                bf162 H0; H0.x = h0; H0.y = h1;
                bf162 L0; L0.x = l0; L0.y = l1;
                *(bf162*)(Chi + o0) = H0;
                *(bf162*)(Clo + o0) = L0;
                split1(v1.x, h0, l0); split1(v1.y, h1, l1);
                bf162 H1; H1.x = h0; H1.y = h1;
                bf162 L1; L1.x = l0; L1.y = l1;
                *(bf162*)(Chi + o1) = H1;
                *(bf162*)(Clo + o1) = L1;
            } else {
                *(float2*)&C[o0] = v0;
                *(float2*)&C[o1] = v1;
            }
        }
    }
}

// ---------------- HMMA flash attention (split bf16, ALiBi) -------------------
#define ATT_SMEM 65536
__global__ __launch_bounds__(128) void flash_attn_mma_kernel(
    const bf16* __restrict__ qkh, const bf16* __restrict__ qkl,
    const float* __restrict__ log_slopes,
    bf16* __restrict__ out_hi, bf16* __restrict__ out_lo)
{
    extern __shared__ __align__(16) char asmem[];
    uint32_t sb = smem_u32(asmem);
    const int QW = 3 * DM;
    int qt = blockIdx.x, hh = blockIdx.y, b = blockIdx.z;
    int tid = threadIdx.x, wid = tid >> 5, lane = tid & 31;
    int wm = wid * 32;
    int grp = lane >> 2, tig = lane & 3;
    float slope = __expf(log_slopes[hh]);
    const float scale = 0.14433756729740643f;  // 1/sqrt(48)
    size_t rbase = (size_t)(b * SEQ + qt * 128);

    #pragma unroll
    for (int i = 0; i < 6; i++) {
        int j = i * 128 + tid;
        int r = j / 6, c = j - r * 6;
        uint32_t dst = (uint32_t)(r * 128 + ((c ^ (r & 3)) << 4));
        size_t g = (rbase + r) * QW + hh * HDIM + c * 8;
        cp16(sb + dst, qkh + g);
        cp16(sb + 16384 + dst, qkl + g);
    }
    CP_COMMIT(); CP_WAIT0();
    __syncthreads();

    uint32_t qfh[2][3][4], qfl[2][3][4];
    #pragma unroll
    for (int mt = 0; mt < 2; mt++)
        #pragma unroll
        for (int ks = 0; ks < 3; ks++) {
            int r = wm + mt * 16 + (lane & 15);
            int c = ks * 2 + (lane >> 4);
            uint32_t off = (uint32_t)(r * 128 + ((c ^ (r & 3)) << 4));
            ldsm4(qfh[mt][ks][0], qfh[mt][ks][1], qfh[mt][ks][2], qfh[mt][ks][3],
                  sb + off);
            ldsm4(qfl[mt][ks][0], qfl[mt][ks][1], qfl[mt][ks][2], qfl[mt][ks][3],
                  sb + 16384 + off);
        }
    __syncthreads();

    float oacc[2][6][4];
    #pragma unroll
    for (int mt = 0; mt < 2; mt++)
        #pragma unroll
        for (int nt = 0; nt < 6; nt++)
            #pragma unroll
            for (int q = 0; q < 4; q++) oacc[mt][nt][q] = 0.f;
    float m_run[4], l_run[4];
    #pragma unroll
    for (int rr = 0; rr < 4; rr++) { m_run[rr] = -INFINITY; l_run[rr] = 0.f; }

    auto issueKV = [&](int kt) {
        uint32_t st = sb + (uint32_t)((kt & 1) * 32768);
        #pragma unroll
        for (int i = 0; i < 12; i++) {
            int j = i * 128 + tid;
            int mat = j / 384;
            int rem = j - mat * 384;
            int rr = rem / 6;
            int cc = rem - rr * 6;
            uint32_t dst = st + (uint32_t)(mat * 8192)
                         + (uint32_t)(rr * 128 + ((cc ^ (rr & 3)) << 4));
            size_t g = (size_t)(b * SEQ + kt * 64 + rr) * QW + hh * HDIM
                     + ((mat < 2) ? DM : 2 * DM) + cc * 8;
            const bf16* src = (mat & 1) ? qkl : qkh;
            cp16(dst, src + g);
        }
        CP_COMMIT();
    };

    issueKV(0);
    for (int kt = 0; kt < SEQ / 64; kt++) {
        if (kt + 1 < SEQ / 64) { issueKV(kt + 1); CP_WAIT1(); }
        else                   { CP_WAIT0(); }
        __syncthreads();
        uint32_t st = sb + (uint32_t)((kt & 1) * 32768);

        float s[2][8][4];
        #pragma unroll
        for (int mt = 0; mt < 2; mt++)
            #pragma unroll
            for (int nt = 0; nt < 8; nt++)
                #pragma unroll
                for (int q = 0; q < 4; q++) s[mt][nt][q] = 0.f;

        #pragma unroll
        for (int ks = 0; ks < 3; ks++) {
            uint32_t bh[8][2], bl[8][2];
            #pragma unroll
            for (int p = 0; p < 4; p++) {
                int n = p * 16 + (lane & 7) + ((lane >> 4) << 3);
                int c = ks * 2 + ((lane >> 3) & 1);
                uint32_t off = (uint32_t)(n * 128 + ((c ^ (n & 3)) << 4));
                ldsm4(bh[2*p][0], bh[2*p][1], bh[2*p+1][0], bh[2*p+1][1], st + off);
                ldsm4(bl[2*p][0], bl[2*p][1], bl[2*p+1][0], bl[2*p+1][1], st + 8192 + off);
            }
            #pragma unroll
            for (int mt = 0; mt < 2; mt++)
                #pragma unroll
                for (int nt = 0; nt < 8; nt++) {
                    mma16816(s[mt][nt], qfh[mt][ks], bh[nt]);
                    mma16816(s[mt][nt], qfh[mt][ks], bl[nt]);
                    mma16816(s[mt][nt], qfl[mt][ks], bh[nt]);
                }
        }

        float corr[4];
        #pragma unroll
        for (int rr = 0; rr < 4; rr++) {
            int mt = rr >> 1, half = rr & 1;
            int qrow = qt * 128 + wm + mt * 16 + half * 8 + grp;
            float mx = -INFINITY;
            #pragma unroll
            for (int nt = 0; nt < 8; nt++)
                #pragma unroll
                for (int jx = 0; jx < 2; jx++) {
                    int c = half * 2 + jx;
                    int kcol = kt * 64 + nt * 8 + tig * 2 + jx;
                    float v = s[mt][nt][c] * scale
                              - slope * fabsf((float)(qrow - kcol));
                    s[mt][nt][c] = v;
                    mx = fmaxf(mx, v);
                }
            mx = fmaxf(mx, __shfl_xor_sync(0xFFFFFFFFu, mx, 1));
            mx = fmaxf(mx, __shfl_xor_sync(0xFFFFFFFFu, mx, 2));
            float newm = fmaxf(m_run[rr], mx);
            corr[rr] = __expf(m_run[rr] - newm);
            m_run[rr] = newm;
            float ps = 0.f;
            #pragma unroll
            for (int nt = 0; nt < 8; nt++)
                #pragma unroll
                for (int jx = 0; jx < 2; jx++) {
                    int c = half * 2 + jx;
                    float p = __expf(s[mt][nt][c] - newm);
                    s[mt][nt][c] = p;
                    ps += p;
                }
            ps += __shfl_xor_sync(0xFFFFFFFFu, ps, 1);
            ps += __shfl_xor_sync(0xFFFFFFFFu, ps, 2);
            l_run[rr] = l_run[rr] * corr[rr] + ps;
        }
        #pragma unroll
        for (int mt = 0; mt < 2; mt++)
            #pragma unroll
            for (int nt = 0; nt < 6; nt++) {
                oacc[mt][nt][0] *= corr[mt*2];     oacc[mt][nt][1] *= corr[mt*2];
                oacc[mt][nt][2] *= corr[mt*2 + 1]; oacc[mt][nt][3] *= corr[mt*2 + 1];
            }

        #pragma unroll
        for (int ks2 = 0; ks2 < 4; ks2++) {
            uint32_t pah[2][4], pal[2][4];
            #pragma unroll
            for (int mt = 0; mt < 2; mt++)
                #pragma unroll
                for (int q2 = 0; q2 < 4; q2++) {
                    int nt = 2 * ks2 + (q2 >> 1);
                    int cb = (q2 & 1) * 2;
                    float v0 = s[mt][nt][cb], v1 = s[mt][nt][cb + 1];
                    bf162 H = __floats2bfloat162_rn(v0, v1);
                    float h0 = __bfloat162float(H.x), h1 = __bfloat162float(H.y);
                    bf162 L = __floats2bfloat162_rn(v0 - h0, v1 - h1);
                    pah[mt][q2] = *(uint32_t*)&H;
                    pal[mt][q2] = *(uint32_t*)&L;
                }
            uint32_t vh[6][2], vl[6][2];
            #pragma unroll
            for (int vt = 0; vt < 3; vt++) {
                int r = ks2 * 16 + (lane & 15);
                int c = vt * 2 + (lane >> 4);
                uint32_t off = (uint32_t)(r * 128 + ((c ^ (r & 3)) << 4));
                ldsm4t(vh[2*vt][0], vh[2*vt][1], vh[2*vt+1][0], vh[2*vt+1][1],
                       st + 16384 + off);
                ldsm4t(vl[2*vt][0], vl[2*vt][1], vl[2*vt+1][0], vl[2*vt+1][1],
                       st + 24576 + off);
            }
            #pragma unroll
            for (int mt = 0; mt < 2; mt++)
                #pragma unroll
                for (int nt = 0; nt < 6; nt++) {
                    mma16816(oacc[mt][nt], pah[mt], vh[nt]);
                    mma16816(oacc[mt][nt], pah[mt], vl[nt]);
                    mma16816(oacc[mt][nt], pal[mt], vh[nt]);
                }
        }
        __syncthreads();
    }

    #pragma unroll
    for (int mt = 0; mt < 2; mt++) {
        float inv0 = 1.0f / l_run[mt*2];
        float inv1 = 1.0f / l_run[mt*2 + 1];
        size_t row0 = (rbase + wm + mt * 16 + grp) * DM + hh * HDIM + tig * 2;
        size_t row1 = row0 + 8 * DM;
        #pragma unroll
        for (int nt = 0; nt < 6; nt++) {
            float v00 = oacc[mt][nt][0] * inv0, v01 = oacc[mt][nt][1] * inv0;
            float v10 = oacc[mt][nt][2] * inv1, v11 = oacc[mt][nt][3] * inv1;
            bf16 h0, l0, h1, l1;
            split1(v00, h0, l0); split1(v01, h1, l1);
            bf162 H0; H0.x = h0; H0.y = h1;
            bf162 L0; L0.x = l0; L0.y = l1;
            *(bf162*)(out_hi + row0 + nt * 8) = H0;
            *(bf162*)(out_lo + row0 + nt * 8) = L0;
            split1(v10, h0, l0); split1(v11, h1, l1);
            bf162 H1; H1.x = h0; H1.y = h1;
            bf162 L1; L1.x = l0; L1.y = l1;
            *(bf162*)(out_hi + row1 + nt * 8) = H1;
            *(bf162*)(out_lo + row1 + nt * 8) = L1;
        }
    }
}

// ---------------- silu(gate)*up with fused bf16 split ------------------------
__global__ void silu_split_kernel(const float4* __restrict__ g,
                                  const float4* __restrict__ u,
                                  bf162* __restrict__ ohi, bf162* __restrict__ olo,
                                  int n4)
{
    int i = blockIdx.x * blockDim.x + threadIdx.x;
    if (i >= n4) return;
    float4 gv = g[i], uv = u[i];
    float y0 = uv.x * gv.x / (1.0f + __expf(-gv.x));
    float y1 = uv.y * gv.y / (1.0f + __expf(-gv.y));
    float y2 = uv.z * gv.z / (1.0f + __expf(-gv.z));
    float y3 = uv.w * gv.w / (1.0f + __expf(-gv.w));
    bf16 h0, l0, h1, l1, h2, l2, h3, l3;
    split1(y0, h0, l0); split1(y1, h1, l1);
    split1(y2, h2, l2); split1(y3, h3, l3);
    bf162 H0; H0.x = h0; H0.y = h1;
    bf162 H1; H1.x = h2; H1.y = h3;
    bf162 L0; L0.x = l0; L0.y = l1;
    bf162 L1; L1.x = l2; L1.y = l3;
    ohi[i * 2] = H0; ohi[i * 2 + 1] = H1;
    olo[i * 2] = L0; olo[i * 2 + 1] = L1;
}

// ---------------- host orchestration ----------------------------------------
static void run_gemm(int mode, const bf16* ah, const bf16* al,
                     const bf16* bh, const bf16* bl,
                     const float* cin, float* c, bf16* chi, bf16* clo,
                     int M, int N, int K)
{
    dim3 grid(N / 128, M / 128);
    if (mode == 0)
        mma_gemm_kernel<0><<<grid, 256, GEMM_SMEM>>>(ah, al, bh, bl, cin, c,
                                                     chi, clo, M, N, K);
    else if (mode == 1)
        mma_gemm_kernel<1><<<grid, 256, GEMM_SMEM>>>(ah, al, bh, bl, cin, c,
                                                     chi, clo, M, N, K);
    else
        mma_gemm_kernel<2><<<grid, 256, GEMM_SMEM>>>(ah, al, bh, bl, cin, c,
                                                     chi, clo, M, N, K);
}

extern "C" void kernel_launch(void* const* d_in, const int* in_sizes, int n_in,
                              void* d_out, int out_size)
{
    const float* cls_tokens = (const float*)d_in[0];
    const float* cls_token  = (const float*)d_in[1];
    const float* log_slopes = (const float*)d_in[2];
    const float* Wqkv       = (const float*)d_in[3];
    const float* Wo         = (const float*)d_in[4];
    const float* Wg         = (const float*)d_in[5];
    const float* Wu         = (const float*)d_in[6];
    const float* Wd         = (const float*)d_in[7];
    const float* ln1w       = (const float*)d_in[8];
    const float* ln1b       = (const float*)d_in[9];
    const float* ln2w       = (const float*)d_in[10];
    const float* ln2b       = (const float*)d_in[11];
    const float* finw       = (const float*)d_in[12];
    const float* finb       = (const float*)d_in[13];
    float* out = (float*)d_out;

    cudaFuncSetAttribute(mma_gemm_kernel<0>,
                         cudaFuncAttributeMaxDynamicSharedMemorySize, GEMM_SMEM);
    cudaFuncSetAttribute(mma_gemm_kernel<1>,
                         cudaFuncAttributeMaxDynamicSharedMemorySize, GEMM_SMEM);
    cudaFuncSetAttribute(mma_gemm_kernel<2>,
                         cudaFuncAttributeMaxDynamicSharedMemorySize, GEMM_SMEM);
    cudaFuncSetAttribute(flash_attn_mma_kernel,
                         cudaFuncAttributeMaxDynamicSharedMemorySize, ATT_SMEM);

    float *x, *gate, *up;
    bf16 *qkvh, *qkvl;
    bf16 *h_hi, *h_lo, *at_hi, *at_lo, *gg_hi, *gg_lo;
    bf16 *wqkv_hi, *wqkv_lo, *wo_hi, *wo_lo, *wg_hi, *wg_lo,
         *wu_hi, *wu_lo, *wd_hi, *wd_lo;
    cudaGetSymbolAddress((void**)&x,    g_x);
    cudaGetSymbolAddress((void**)&gate, g_gate);
    cudaGetSymbolAddress((void**)&up,   g_up);
    cudaGetSymbolAddress((void**)&qkvh, g_qkvh);
    cudaGetSymbolAddress((void**)&qkvl, g_qkvl);
    cudaGetSymbolAddress((void**)&h_hi, g_h_hi);
    cudaGetSymbolAddress((void**)&h_lo, g_h_lo);
    cudaGetSymbolAddress((void**)&at_hi, g_at_hi);
    cudaGetSymbolAddress((void**)&at_lo, g_at_lo);
    cudaGetSymbolAddress((void**)&gg_hi, g_g_hi);
    cudaGetSymbolAddress((void**)&gg_lo, g_g_lo);
    cudaGetSymbolAddress((void**)&wqkv_hi, g_wqkv_hi);
    cudaGetSymbolAddress((void**)&wqkv_lo, g_wqkv_lo);
    cudaGetSymbolAddress((void**)&wo_hi, g_wo_hi);
    cudaGetSymbolAddress((void**)&wo_lo, g_wo_lo);
    cudaGetSymbolAddress((void**)&wg_hi, g_wg_hi);
    cudaGetSymbolAddress((void**)&wg_lo, g_wg_lo);
    cudaGetSymbolAddress((void**)&wu_hi, g_wu_hi);
    cudaGetSymbolAddress((void**)&wu_lo, g_wu_lo);
    cudaGetSymbolAddress((void**)&wd_hi, g_wd_hi);
    cudaGetSymbolAddress((void**)&wd_lo, g_wd_lo);

    // single combined weight split (keeps ncu -s 5 capture on a GEMM launch)
    split_all_kernel<<<(N4_ALL + 255) / 256, 256>>>(
        (const float4*)Wqkv, (const float4*)Wo, (const float4*)Wg,
        (const float4*)Wu, (const float4*)Wd);

    build_x_kernel<<<(MTOK * DM + 255) / 256, 256>>>(cls_tokens, cls_token, x);

    for (int l = 0; l < LAYERS; l++) {
        size_t oq = (size_t)l * 3 * DM * DM;
        size_t oo = (size_t)l * DM * DM;
        size_t og = (size_t)l * FFDIM * DM;
        size_t od = (size_t)l * DM * FFDIM;

        layernorm_split_kernel<<<MTOK, 256>>>(x, h_hi, h_lo,
                                              ln1w + l * DM, ln1b + l * DM);

        run_gemm(2, h_hi, h_lo, wqkv_hi + oq, wqkv_lo + oq,
                 nullptr, nullptr, qkvh, qkvl, MTOK, 3 * DM, DM);

        flash_attn_mma_kernel<<<dim3(SEQ / 128, NH, BATCH), 128, ATT_SMEM>>>(
            qkvh, qkvl, log_slopes, at_hi, at_lo);

        run_gemm(1, at_hi, at_lo, wo_hi + oo, wo_lo + oo,
                 x, x, nullptr, nullptr, MTOK, DM, DM);

        layernorm_split_kernel<<<MTOK, 256>>>(x, h_hi, h_lo,
                                              ln2w + l * DM, ln2b + l * DM);

        run_gemm(0, h_hi, h_lo, wg_hi + og, wg_lo + og,
                 nullptr, gate, nullptr, nullptr, MTOK, FFDIM, DM);
        run_gemm(0, h_hi, h_lo, wu_hi + og, wu_lo + og,
                 nullptr, up, nullptr, nullptr, MTOK, FFDIM, DM);

        int n4 = MTOK * FFDIM / 4;
        silu_split_kernel<<<(n4 + 255) / 256, 256>>>(
            (const float4*)gate, (const float4*)up,
            (bf162*)gg_hi, (bf162*)gg_lo, n4);

        run_gemm(1, gg_hi, gg_lo, wd_hi + od, wd_lo + od,
                 x, x, nullptr, nullptr, MTOK, DM, FFDIM);
    }

    layernorm_kernel<<<BATCH, 256>>>(x, (size_t)SEQ * DM, out, finw, finb);
}